// round 1
// baseline (speedup 1.0000x reference)
#include <cuda_runtime.h>
#include <cuda_bf16.h>

// Problem constants (fixed by the reference)
#define B_ROWS  16384
#define D_DIM   784
#define C_DIM   2048
#define OUT_DIM 10

// Tiling
#define TM 64
#define TN 128
#define TK 16
#define NTHREADS 256
#define KTILES (D_DIM / TK)   // 49

// Scratch (no allocations allowed -> device globals)
__device__ float g_x2[B_ROWS];
__device__ float g_c2[C_DIM];
__device__ float g_is2[C_DIM];

// ---------------------------------------------------------------------------
// Row squared norms of x (one warp per row, coalesced)
// ---------------------------------------------------------------------------
__global__ void row_norm_x_kernel(const float* __restrict__ x) {
    int warp = (blockIdx.x * blockDim.x + threadIdx.x) >> 5;
    int lane = threadIdx.x & 31;
    if (warp >= B_ROWS) return;
    const float* row = x + (size_t)warp * D_DIM;
    float s = 0.f;
    for (int j = lane; j < D_DIM; j += 32) {
        float v = row[j];
        s = fmaf(v, v, s);
    }
    #pragma unroll
    for (int m = 16; m; m >>= 1) s += __shfl_xor_sync(0xffffffffu, s, m);
    if (lane == 0) g_x2[warp] = s;
}

// Row squared norms of centres + inv sigma^2 = exp(-2*log_sigma)
__global__ void row_norm_c_kernel(const float* __restrict__ c,
                                  const float* __restrict__ log_sigmas) {
    int warp = (blockIdx.x * blockDim.x + threadIdx.x) >> 5;
    int lane = threadIdx.x & 31;
    if (warp >= C_DIM) return;
    const float* row = c + (size_t)warp * D_DIM;
    float s = 0.f;
    for (int j = lane; j < D_DIM; j += 32) {
        float v = row[j];
        s = fmaf(v, v, s);
    }
    #pragma unroll
    for (int m = 16; m; m >>= 1) s += __shfl_xor_sync(0xffffffffu, s, m);
    if (lane == 0) {
        g_c2[warp]  = s;
        g_is2[warp] = __expf(-2.f * log_sigmas[warp]);
    }
}

// ---------------------------------------------------------------------------
// Fused main kernel: for a 64-row tile of x, loop over all C centres in
// chunks of 128. Per chunk: 64x128x784 fp32 GEMM (4x8 register blocking,
// TK=16, double-buffered smem), phi = exp(-d2/sigma^2) into smem, then
// phi @ W_chunk^T accumulated into per-thread registers.
// ---------------------------------------------------------------------------
__global__ __launch_bounds__(NTHREADS)
void rbf_main_kernel(const float* __restrict__ x,
                     const float* __restrict__ centres,
                     const float* __restrict__ W,
                     const float* __restrict__ bias,
                     float* __restrict__ out) {
    extern __shared__ float sm[];
    float* As   = sm;                       // [2][TK][TM]   2048 floats
    float* Bs   = As + 2 * TK * TM;         // [2][TK][TN]   4096 floats
    float* phiS = Bs + 2 * TK * TN;         // [TM][TN+1]    8256 floats (pad -> conflict-free)
    float* WcS  = phiS + TM * (TN + 1);     // [OUT][TN]     1280 floats
    float* c2S  = WcS + OUT_DIM * TN;       // [TN]
    float* is2S = c2S + TN;                 // [TN]
    float* x2S  = is2S + TN;                // [TM]

    const int tid = threadIdx.x;
    const int tx  = tid & 15;               // 0..15 -> 8 centre-cols each
    const int ty  = tid >> 4;               // 0..15 -> 4 x-rows each
    const int m0  = blockIdx.x * TM;

    if (tid < TM) x2S[tid] = g_x2[m0 + tid];

    // Output accumulators: 640 outputs / 256 threads -> up to 3 per thread
    float oacc[3] = {0.f, 0.f, 0.f};

    // A tile load mapping: one float4 per thread per k-tile
    const int a_m = tid >> 2;               // 0..63
    const int a_k = (tid & 3) * 4;          // 0,4,8,12
    // B tile load mapping: two float4 per thread per k-tile
    const int b_n0 = tid >> 2;              // 0..63
    const int b_n1 = (tid + NTHREADS) >> 2; // 64..127
    const int b_k  = (tid & 3) * 4;

    for (int n0 = 0; n0 < C_DIM; n0 += TN) {
        // Per-chunk metadata
        if (tid < TN) {
            c2S[tid]  = g_c2[n0 + tid];
            is2S[tid] = g_is2[n0 + tid];
        }
        for (int idx = tid; idx < OUT_DIM * TN; idx += NTHREADS) {
            int o = idx >> 7;           // /128
            int j = idx & (TN - 1);
            WcS[idx] = W[(size_t)o * C_DIM + n0 + j];
        }
        __syncthreads();

        float acc[4][8];
        #pragma unroll
        for (int i = 0; i < 4; i++)
            #pragma unroll
            for (int j = 0; j < 8; j++) acc[i][j] = 0.f;

        // Preload k-tile 0 into buffer 0
        {
            float4 aR  = *(const float4*)&x[(size_t)(m0 + a_m) * D_DIM + a_k];
            float4 bR0 = *(const float4*)&centres[(size_t)(n0 + b_n0) * D_DIM + b_k];
            float4 bR1 = *(const float4*)&centres[(size_t)(n0 + b_n1) * D_DIM + b_k];
            float* A0 = As;
            A0[(a_k + 0) * TM + a_m] = aR.x;
            A0[(a_k + 1) * TM + a_m] = aR.y;
            A0[(a_k + 2) * TM + a_m] = aR.z;
            A0[(a_k + 3) * TM + a_m] = aR.w;
            float* B0 = Bs;
            B0[(b_k + 0) * TN + b_n0] = bR0.x;
            B0[(b_k + 1) * TN + b_n0] = bR0.y;
            B0[(b_k + 2) * TN + b_n0] = bR0.z;
            B0[(b_k + 3) * TN + b_n0] = bR0.w;
            B0[(b_k + 0) * TN + b_n1] = bR1.x;
            B0[(b_k + 1) * TN + b_n1] = bR1.y;
            B0[(b_k + 2) * TN + b_n1] = bR1.z;
            B0[(b_k + 3) * TN + b_n1] = bR1.w;
        }
        __syncthreads();

        for (int t = 0; t < KTILES; t++) {
            const int cur = t & 1;
            float4 aN, bN0, bN1;
            const bool more = (t + 1 < KTILES);
            if (more) {
                int k0 = (t + 1) * TK;
                aN  = *(const float4*)&x[(size_t)(m0 + a_m) * D_DIM + k0 + a_k];
                bN0 = *(const float4*)&centres[(size_t)(n0 + b_n0) * D_DIM + k0 + b_k];
                bN1 = *(const float4*)&centres[(size_t)(n0 + b_n1) * D_DIM + k0 + b_k];
            }
            const float* Ac = As + cur * TK * TM;
            const float* Bc = Bs + cur * TK * TN;
            #pragma unroll
            for (int k = 0; k < TK; k++) {
                float4 av  = *(const float4*)&Ac[k * TM + ty * 4];
                float4 bv0 = *(const float4*)&Bc[k * TN + tx * 8];
                float4 bv1 = *(const float4*)&Bc[k * TN + tx * 8 + 4];
                float a0 = av.x, a1 = av.y, a2 = av.z, a3 = av.w;
                float bb[8] = {bv0.x, bv0.y, bv0.z, bv0.w,
                               bv1.x, bv1.y, bv1.z, bv1.w};
                #pragma unroll
                for (int j = 0; j < 8; j++) {
                    acc[0][j] = fmaf(a0, bb[j], acc[0][j]);
                    acc[1][j] = fmaf(a1, bb[j], acc[1][j]);
                    acc[2][j] = fmaf(a2, bb[j], acc[2][j]);
                    acc[3][j] = fmaf(a3, bb[j], acc[3][j]);
                }
            }
            if (more) {
                const int nxt = cur ^ 1;
                float* An = As + nxt * TK * TM;
                An[(a_k + 0) * TM + a_m] = aN.x;
                An[(a_k + 1) * TM + a_m] = aN.y;
                An[(a_k + 2) * TM + a_m] = aN.z;
                An[(a_k + 3) * TM + a_m] = aN.w;
                float* Bn = Bs + nxt * TK * TN;
                Bn[(b_k + 0) * TN + b_n0] = bN0.x;
                Bn[(b_k + 1) * TN + b_n0] = bN0.y;
                Bn[(b_k + 2) * TN + b_n0] = bN0.z;
                Bn[(b_k + 3) * TN + b_n0] = bN0.w;
                Bn[(b_k + 0) * TN + b_n1] = bN1.x;
                Bn[(b_k + 1) * TN + b_n1] = bN1.y;
                Bn[(b_k + 2) * TN + b_n1] = bN1.z;
                Bn[(b_k + 3) * TN + b_n1] = bN1.w;
                __syncthreads();
            }
        }

        // phi = exp(-max(x2 + c2 - 2*dot, 0) * inv_sigma2) into padded smem
        #pragma unroll
        for (int i = 0; i < 4; i++) {
            int r = ty * 4 + i;
            float xv = x2S[r];
            #pragma unroll
            for (int j = 0; j < 8; j++) {
                int cix = tx * 8 + j;
                float d2 = fmaxf(xv + c2S[cix] - 2.f * acc[i][j], 0.f);
                phiS[r * (TN + 1) + cix] = __expf(-d2 * is2S[cix]);
            }
        }
        __syncthreads();

        // out_partial[r][o] += sum_j phi[r][j] * W[o][n0+j]
        {
            int slot = 0;
            for (int e = tid; e < TM * OUT_DIM; e += NTHREADS, slot++) {
                int r = e & (TM - 1);
                int o = e >> 6;
                const float* pr = phiS + r * (TN + 1);
                const float* wr = WcS + o * TN;
                float s = 0.f;
                #pragma unroll 8
                for (int j = 0; j < TN; j++) s = fmaf(pr[j], wr[j], s);
                oacc[slot] += s;
            }
        }
        __syncthreads();   // protect phiS / c2S / WcS before next chunk
    }

    // Final write: out = acc + bias
    {
        int slot = 0;
        for (int e = tid; e < TM * OUT_DIM; e += NTHREADS, slot++) {
            int r = e & (TM - 1);
            int o = e >> 6;
            out[(size_t)(m0 + r) * OUT_DIM + o] = oacc[slot] + bias[o];
        }
    }
}

// ---------------------------------------------------------------------------
// Launch
// ---------------------------------------------------------------------------
extern "C" void kernel_launch(void* const* d_in, const int* in_sizes, int n_in,
                              void* d_out, int out_size) {
    const float* x       = (const float*)d_in[0];
    const float* centres = (const float*)d_in[1];
    const float* ls      = (const float*)d_in[2];
    const float* W       = (const float*)d_in[3];
    const float* bias    = (const float*)d_in[4];
    float* out           = (float*)d_out;

    // Row norms: one warp per row, 8 warps per block
    row_norm_x_kernel<<<B_ROWS / 8, 256>>>(x);
    row_norm_c_kernel<<<C_DIM / 8, 256>>>(centres, ls);

    const int smem_bytes = (2 * TK * TM + 2 * TK * TN + TM * (TN + 1) +
                            OUT_DIM * TN + TN + TN + TM) * (int)sizeof(float);
    cudaFuncSetAttribute(rbf_main_kernel,
                         cudaFuncAttributeMaxDynamicSharedMemorySize, smem_bytes);
    rbf_main_kernel<<<B_ROWS / TM, NTHREADS, smem_bytes>>>(x, centres, W, bias, out);
}

// round 3
// speedup vs baseline: 6.1100x; 6.1100x over previous
#include <cuda_runtime.h>
#include <cuda_bf16.h>
#include <cstdint>

// ---------------------------------------------------------------------------
// Problem constants
// ---------------------------------------------------------------------------
#define B_ROWS  16384
#define D_DIM   784
#define C_DIM   2048
#define OUT_DIM 10

#define KPAD  832                // 784 padded to 13*64
#define KB    64                 // K elems per cp.async block
#define NKB   13
#define TM    128                // x rows per CTA
#define TN    128                // centres per chunk
#define NCHUNK (C_DIM / TN)      // 16
#define NTHREADS 256

// smem strides
#define AST   72                 // bf16 elems per A/B smem row (64 + 8 pad)
#define ASTB  144                // bytes
#define PHIST 136                // f32 elems per phi row (128 + 8 pad)

// smem byte offsets
#define OFF_A    0u              // 2 x 128 x 144        = 36864
#define OFF_B    36864u          // 2 x 128 x 144        = 36864
#define OFF_PHI  73728u          // 128 x 136 x 4        = 69632
#define OFF_W    143360u         // 10 x 128 x 4         = 5120
#define OFF_X2   148480u         // 128 x 4
#define OFF_C2   148992u
#define OFF_IS2  149504u
#define SMEM_TOTAL 150016u

// ---------------------------------------------------------------------------
// Device-global scratch (no allocations allowed)
// ---------------------------------------------------------------------------
__device__ __align__(16) __nv_bfloat16 g_xb[(size_t)B_ROWS * KPAD];  // 27.3 MB
__device__ __align__(16) __nv_bfloat16 g_cb[(size_t)C_DIM * KPAD];   // 3.4 MB
__device__ float g_x2[B_ROWS];
__device__ float g_c2[C_DIM];
__device__ float g_is2[C_DIM];

// ---------------------------------------------------------------------------
// PTX helpers (portable: sm_80-era instructions only, no arch-specific feats)
// ---------------------------------------------------------------------------
__device__ __forceinline__ uint32_t smem_u32(const void* p) {
    uint32_t a;
    asm("{ .reg .u64 t; cvta.to.shared.u64 t, %1; cvt.u32.u64 %0, t; }" : "=r"(a) : "l"(p));
    return a;
}

__device__ __forceinline__ void cp16(uint32_t dst, const void* src) {
    asm volatile("cp.async.cg.shared.global [%0], [%1], 16;" :: "r"(dst), "l"(src));
}
#define CP_COMMIT() asm volatile("cp.async.commit_group;" ::: "memory")
#define CP_WAIT0()  asm volatile("cp.async.wait_group 0;"  ::: "memory")

__device__ __forceinline__ void ldm_x4(uint32_t* r, uint32_t addr) {
    asm volatile("ldmatrix.sync.aligned.m8n8.x4.shared.b16 {%0,%1,%2,%3}, [%4];"
                 : "=r"(r[0]), "=r"(r[1]), "=r"(r[2]), "=r"(r[3]) : "r"(addr));
}

__device__ __forceinline__ void mma16816(float* c, const uint32_t* a, const uint32_t* b) {
    asm volatile(
        "mma.sync.aligned.m16n8k16.row.col.f32.bf16.bf16.f32 "
        "{%0,%1,%2,%3}, {%4,%5,%6,%7}, {%8,%9}, {%0,%1,%2,%3};"
        : "+f"(c[0]), "+f"(c[1]), "+f"(c[2]), "+f"(c[3])
        : "r"(a[0]), "r"(a[1]), "r"(a[2]), "r"(a[3]), "r"(b[0]), "r"(b[1]));
}

// ---------------------------------------------------------------------------
// Prep: convert to padded bf16 + row squared norms (fused). One warp per row.
// ---------------------------------------------------------------------------
__global__ void prep_x_kernel(const float* __restrict__ x) {
    int row  = (blockIdx.x * blockDim.x + threadIdx.x) >> 5;
    int lane = threadIdx.x & 31;
    if (row >= B_ROWS) return;
    const float* src = x + (size_t)row * D_DIM;
    __nv_bfloat16* dst = g_xb + (size_t)row * KPAD;
    float s = 0.f;
    for (int j = lane; j < KPAD; j += 32) {
        float v = (j < D_DIM) ? src[j] : 0.f;
        s = fmaf(v, v, s);
        dst[j] = __float2bfloat16(v);
    }
    #pragma unroll
    for (int m = 16; m; m >>= 1) s += __shfl_xor_sync(0xffffffffu, s, m);
    if (lane == 0) g_x2[row] = s;
}

__global__ void prep_c_kernel(const float* __restrict__ c, const float* __restrict__ ls) {
    int row  = (blockIdx.x * blockDim.x + threadIdx.x) >> 5;
    int lane = threadIdx.x & 31;
    if (row >= C_DIM) return;
    const float* src = c + (size_t)row * D_DIM;
    __nv_bfloat16* dst = g_cb + (size_t)row * KPAD;
    float s = 0.f;
    for (int j = lane; j < KPAD; j += 32) {
        float v = (j < D_DIM) ? src[j] : 0.f;
        s = fmaf(v, v, s);
        dst[j] = __float2bfloat16(v);
    }
    #pragma unroll
    for (int m = 16; m; m >>= 1) s += __shfl_xor_sync(0xffffffffu, s, m);
    if (lane == 0) { g_c2[row] = s; g_is2[row] = __expf(-2.f * ls[row]); }
}

// ---------------------------------------------------------------------------
// Main fused kernel (mma.sync bf16 tensor cores)
// ---------------------------------------------------------------------------
__global__ __launch_bounds__(NTHREADS, 1)
void rbf_mma_kernel(const float* __restrict__ W,
                    const float* __restrict__ bias,
                    float* __restrict__ out) {
    extern __shared__ char sm[];
    const uint32_t sbase = smem_u32(sm);

    const int tid  = threadIdx.x;
    const int wid  = tid >> 5;
    const int lane = tid & 31;
    const int wm   = wid & 3;        // warp M group: rows wm*32 .. +31
    const int wn   = wid >> 2;       // warp N group: cols wn*64 .. +63
    const int m0   = blockIdx.x * TM;

    float* x2S  = (float*)(sm + OFF_X2);
    float* c2S  = (float*)(sm + OFF_C2);
    float* is2S = (float*)(sm + OFF_IS2);
    float* WcS  = (float*)(sm + OFF_W);
    float* phiS = (float*)(sm + OFF_PHI);

    if (tid < TM) x2S[tid] = g_x2[m0 + tid];

    // cp.async tile-load mapping: 1024 16B-chunks per tile / 256 thr = 4 each
    // idx -> row = idx>>3, ch = idx&7
    const int lm = lane >> 2;            // 0..7
    const int ln = (lane & 3) * 2;       // 0,2,4,6

    float oacc[5] = {0.f, 0.f, 0.f, 0.f, 0.f};

    for (int chunk = 0; chunk < NCHUNK; chunk++) {
        const int n0 = chunk * TN;

        // chunk metadata into smem
        if (tid < TN) {
            c2S[tid]  = g_c2[n0 + tid];
            is2S[tid] = g_is2[n0 + tid];
        }
        for (int idx = tid; idx < OUT_DIM * TN; idx += NTHREADS) {
            int o = idx >> 7, j = idx & (TN - 1);
            WcS[idx] = W[(size_t)o * C_DIM + n0 + j];
        }

        float acc[2][8][4];
        #pragma unroll
        for (int i = 0; i < 2; i++)
            #pragma unroll
            for (int j = 0; j < 8; j++)
                #pragma unroll
                for (int e = 0; e < 4; e++) acc[i][j][e] = 0.f;

        // preload kb = 0 into buf 0
        {
            #pragma unroll
            for (int i = 0; i < 4; i++) {
                int idx = tid + i * NTHREADS;
                int r = idx >> 3, ch = idx & 7;
                cp16(sbase + OFF_A + (uint32_t)r * ASTB + ch * 16,
                     g_xb + (size_t)(m0 + r) * KPAD + ch * 8);
                cp16(sbase + OFF_B + (uint32_t)r * ASTB + ch * 16,
                     g_cb + (size_t)(n0 + r) * KPAD + ch * 8);
            }
            CP_COMMIT();
        }

        for (int kb = 0; kb < NKB; kb++) {
            const int buf = kb & 1;
            CP_WAIT0();
            __syncthreads();   // buf(kb) visible to all; also fences smem metadata stores

            if (kb + 1 < NKB) {
                const uint32_t obuf = (uint32_t)(buf ^ 1) * 18432u;
                const int koff = (kb + 1) * KB;
                #pragma unroll
                for (int i = 0; i < 4; i++) {
                    int idx = tid + i * NTHREADS;
                    int r = idx >> 3, ch = idx & 7;
                    cp16(sbase + OFF_A + obuf + (uint32_t)r * ASTB + ch * 16,
                         g_xb + (size_t)(m0 + r) * KPAD + koff + ch * 8);
                    cp16(sbase + OFF_B + obuf + (uint32_t)r * ASTB + ch * 16,
                         g_cb + (size_t)(n0 + r) * KPAD + koff + ch * 8);
                }
                CP_COMMIT();
            }

            const uint32_t aBase = sbase + OFF_A + (uint32_t)buf * 18432u;
            const uint32_t bBase = sbase + OFF_B + (uint32_t)buf * 18432u;
            const uint32_t lrow  = (uint32_t)(lane & 15);
            const uint32_t lcol  = (uint32_t)(lane >> 4) * 16u;

            #pragma unroll
            for (int ks = 0; ks < 4; ks++) {
                uint32_t af[2][4];
                #pragma unroll
                for (int mi = 0; mi < 2; mi++)
                    ldm_x4(af[mi], aBase + (uint32_t)(wm * 32 + mi * 16 + lrow) * ASTB
                                         + (uint32_t)ks * 32u + lcol);
                uint32_t bf[8][2];
                #pragma unroll
                for (int njj = 0; njj < 4; njj++) {
                    uint32_t r4[4];
                    ldm_x4(r4, bBase + (uint32_t)(wn * 64 + njj * 16 + lrow) * ASTB
                                     + (uint32_t)ks * 32u + lcol);
                    bf[njj * 2 + 0][0] = r4[0];
                    bf[njj * 2 + 1][0] = r4[1];
                    bf[njj * 2 + 0][1] = r4[2];
                    bf[njj * 2 + 1][1] = r4[3];
                }
                #pragma unroll
                for (int mi = 0; mi < 2; mi++)
                    #pragma unroll
                    for (int nf = 0; nf < 8; nf++)
                        mma16816(acc[mi][nf], af[mi], bf[nf]);
            }
        }

        // ---- epilogue: phi = exp(-max(x2+c2-2*dot,0)*is2) into padded smem ----
        #pragma unroll
        for (int mi = 0; mi < 2; mi++) {
            const int r0 = wm * 32 + mi * 16 + lm;
            const int r1 = r0 + 8;
            const float x2a = x2S[r0];
            const float x2b = x2S[r1];
            #pragma unroll
            for (int nf = 0; nf < 8; nf++) {
                const int c0 = wn * 64 + nf * 8 + ln;
                const float cc0 = c2S[c0],  cc1 = c2S[c0 + 1];
                const float ii0 = is2S[c0], ii1 = is2S[c0 + 1];
                float d;
                float2 pa, pb;
                d = fmaxf(x2a + cc0 - 2.f * acc[mi][nf][0], 0.f) * ii0; pa.x = __expf(-d);
                d = fmaxf(x2a + cc1 - 2.f * acc[mi][nf][1], 0.f) * ii1; pa.y = __expf(-d);
                d = fmaxf(x2b + cc0 - 2.f * acc[mi][nf][2], 0.f) * ii0; pb.x = __expf(-d);
                d = fmaxf(x2b + cc1 - 2.f * acc[mi][nf][3], 0.f) * ii1; pb.y = __expf(-d);
                *(float2*)&phiS[(size_t)r0 * PHIST + c0] = pa;
                *(float2*)&phiS[(size_t)r1 * PHIST + c0] = pb;
            }
        }
        __syncthreads();

        // ---- GEMV: oacc[r][o] += phi[r][:] . W[o][:]  (float4 vectorized) ----
        #pragma unroll
        for (int s = 0; s < 5; s++) {
            const int e = s * NTHREADS + tid;      // 0..1279
            const int r = e / OUT_DIM;
            const int o = e - r * OUT_DIM;
            const float4* pr = (const float4*)&phiS[(size_t)r * PHIST];
            const float4* wr = (const float4*)&WcS[(size_t)o * TN];
            float sum = 0.f;
            #pragma unroll
            for (int j = 0; j < TN / 4; j++) {
                float4 a = pr[j], b = wr[j];
                sum = fmaf(a.x, b.x, sum);
                sum = fmaf(a.y, b.y, sum);
                sum = fmaf(a.z, b.z, sum);
                sum = fmaf(a.w, b.w, sum);
            }
            oacc[s] += sum;
        }
        __syncthreads();   // protect phiS / WcS / c2S before next chunk
    }

    // ---- final write ----
    #pragma unroll
    for (int s = 0; s < 5; s++) {
        const int e = s * NTHREADS + tid;
        const int r = e / OUT_DIM;
        const int o = e - r * OUT_DIM;
        out[(size_t)(m0 + r) * OUT_DIM + o] = oacc[s] + __ldg(&bias[o]);
    }
}

// ---------------------------------------------------------------------------
// Launch
// ---------------------------------------------------------------------------
extern "C" void kernel_launch(void* const* d_in, const int* in_sizes, int n_in,
                              void* d_out, int out_size) {
    const float* x       = (const float*)d_in[0];
    const float* centres = (const float*)d_in[1];
    const float* ls      = (const float*)d_in[2];
    const float* W       = (const float*)d_in[3];
    const float* bias    = (const float*)d_in[4];
    float* out           = (float*)d_out;

    prep_x_kernel<<<B_ROWS / 8, 256>>>(x);
    prep_c_kernel<<<C_DIM / 8, 256>>>(centres, ls);

    cudaFuncSetAttribute(rbf_mma_kernel,
                         cudaFuncAttributeMaxDynamicSharedMemorySize, SMEM_TOTAL);
    rbf_mma_kernel<<<B_ROWS / TM, NTHREADS, SMEM_TOTAL>>>(W, bias, out);
}

// round 4
// speedup vs baseline: 13.0676x; 2.1387x over previous
#include <cuda_runtime.h>
#include <cuda_bf16.h>
#include <cstdint>

// ---------------------------------------------------------------------------
// Problem constants
// ---------------------------------------------------------------------------
#define B_ROWS  16384
#define D_DIM   784
#define C_DIM   2048
#define OUT_DIM 10

#define KPAD  832                // 784 padded to 13*64
#define KB    64                 // K elems per cp.async block
#define NKB   13
#define TM    128                // x rows per CTA
#define TN    128                // centres per chunk
#define NCHUNK (C_DIM / TN)      // 16
#define NGBLK  (NCHUNK * NKB)    // 208 flattened k-blocks
#define NTHREADS 256

// smem strides
#define AST   72                 // bf16 elems per A/B smem row (64 + 8 pad)
#define ASTB  144                // bytes
#define WST   12                 // floats per Wcol row (10 + 2 pad)

// smem byte offsets
#define OFF_A    0u              // 2 x 128 x 144 = 36864
#define OFF_B    36864u          // 2 x 128 x 144 = 36864
#define OFF_WCOL 73728u          // 128 x 12 x 4  = 6144
#define OFF_X2   79872u          // 128 x 4
#define OFF_C2   80384u          // 128 x 4
#define OFF_IS2  80896u          // 128 x 4
#define SMEM_TOTAL 81408u
// final reduction buffer overlays OFF_A (used only after last chunk)
#define OFF_RED  OFF_A           // 128 x 12 x 4 = 6144

// ---------------------------------------------------------------------------
// Device-global scratch (no allocations allowed)
// ---------------------------------------------------------------------------
__device__ __align__(16) __nv_bfloat16 g_xb[(size_t)B_ROWS * KPAD];  // 27.3 MB
__device__ __align__(16) __nv_bfloat16 g_cb[(size_t)C_DIM * KPAD];   // 3.4 MB
__device__ float g_x2[B_ROWS];
__device__ float g_c2[C_DIM];
__device__ float g_is2[C_DIM];

// ---------------------------------------------------------------------------
// PTX helpers (portable sm_80-era only; compute_103 virtual target compatible)
// ---------------------------------------------------------------------------
__device__ __forceinline__ uint32_t smem_u32(const void* p) {
    uint32_t a;
    asm("{ .reg .u64 t; cvta.to.shared.u64 t, %1; cvt.u32.u64 %0, t; }" : "=r"(a) : "l"(p));
    return a;
}

__device__ __forceinline__ void cp16(uint32_t dst, const void* src) {
    asm volatile("cp.async.cg.shared.global [%0], [%1], 16;" :: "r"(dst), "l"(src));
}
#define CP_COMMIT() asm volatile("cp.async.commit_group;" ::: "memory")
#define CP_WAIT0()  asm volatile("cp.async.wait_group 0;"  ::: "memory")

__device__ __forceinline__ void ldm_x4(uint32_t* r, uint32_t addr) {
    asm volatile("ldmatrix.sync.aligned.m8n8.x4.shared.b16 {%0,%1,%2,%3}, [%4];"
                 : "=r"(r[0]), "=r"(r[1]), "=r"(r[2]), "=r"(r[3]) : "r"(addr));
}

__device__ __forceinline__ void mma16816(float* c, const uint32_t* a, const uint32_t* b) {
    asm volatile(
        "mma.sync.aligned.m16n8k16.row.col.f32.bf16.bf16.f32 "
        "{%0,%1,%2,%3}, {%4,%5,%6,%7}, {%8,%9}, {%0,%1,%2,%3};"
        : "+f"(c[0]), "+f"(c[1]), "+f"(c[2]), "+f"(c[3])
        : "r"(a[0]), "r"(a[1]), "r"(a[2]), "r"(a[3]), "r"(b[0]), "r"(b[1]));
}

// ---------------------------------------------------------------------------
// Prep: convert to padded bf16 + row squared norms (fused). One warp per row.
// ---------------------------------------------------------------------------
__global__ void prep_x_kernel(const float* __restrict__ x) {
    int row  = (blockIdx.x * blockDim.x + threadIdx.x) >> 5;
    int lane = threadIdx.x & 31;
    if (row >= B_ROWS) return;
    const float* src = x + (size_t)row * D_DIM;
    __nv_bfloat16* dst = g_xb + (size_t)row * KPAD;
    float s = 0.f;
    for (int j = lane; j < KPAD; j += 32) {
        float v = (j < D_DIM) ? src[j] : 0.f;
        s = fmaf(v, v, s);
        dst[j] = __float2bfloat16(v);
    }
    #pragma unroll
    for (int m = 16; m; m >>= 1) s += __shfl_xor_sync(0xffffffffu, s, m);
    if (lane == 0) g_x2[row] = s;
}

__global__ void prep_c_kernel(const float* __restrict__ c, const float* __restrict__ ls) {
    int row  = (blockIdx.x * blockDim.x + threadIdx.x) >> 5;
    int lane = threadIdx.x & 31;
    if (row >= C_DIM) return;
    const float* src = c + (size_t)row * D_DIM;
    __nv_bfloat16* dst = g_cb + (size_t)row * KPAD;
    float s = 0.f;
    for (int j = lane; j < KPAD; j += 32) {
        float v = (j < D_DIM) ? src[j] : 0.f;
        s = fmaf(v, v, s);
        dst[j] = __float2bfloat16(v);
    }
    #pragma unroll
    for (int m = 16; m; m >>= 1) s += __shfl_xor_sync(0xffffffffu, s, m);
    if (lane == 0) { g_c2[row] = s; g_is2[row] = __expf(-2.f * ls[row]); }
}

// ---------------------------------------------------------------------------
// Main fused kernel: register-resident epilogue, continuous cp.async pipeline
// ---------------------------------------------------------------------------
__global__ __launch_bounds__(NTHREADS, 1)
void rbf_mma_kernel(const float* __restrict__ W,
                    const float* __restrict__ bias,
                    float* __restrict__ out) {
    extern __shared__ char sm[];
    const uint32_t sbase = smem_u32(sm);

    const int tid  = threadIdx.x;
    const int wid  = tid >> 5;
    const int lane = tid & 31;
    const int wm   = wid & 3;        // warp M group: rows wm*32 .. +31
    const int wn   = wid >> 2;       // warp N group: cols wn*64 .. +63
    const int m0   = blockIdx.x * TM;
    const int lm   = lane >> 2;      // 0..7
    const int ln   = (lane & 3) * 2; // 0,2,4,6

    float* x2S   = (float*)(sm + OFF_X2);
    float* c2S   = (float*)(sm + OFF_C2);
    float* is2S  = (float*)(sm + OFF_IS2);
    float* WcolS = (float*)(sm + OFF_WCOL);

    if (tid < TM) x2S[tid] = g_x2[m0 + tid];

    // Per-thread output accumulators: 4 rows x 10 outputs.
    // Row(mi,h) = wm*32 + mi*16 + h*8 + lm (fixed for all chunks).
    float oacc[4][OUT_DIM];
    #pragma unroll
    for (int i = 0; i < 4; i++)
        #pragma unroll
        for (int o = 0; o < OUT_DIM; o++) oacc[i][o] = 0.f;

    // Flattened-pipeline preload: g = 0 -> buf 0
    {
        #pragma unroll
        for (int i = 0; i < 4; i++) {
            int idx = tid + i * NTHREADS;
            int r = idx >> 3, ch = idx & 7;
            cp16(sbase + OFF_A + (uint32_t)r * ASTB + ch * 16,
                 g_xb + (size_t)(m0 + r) * KPAD + ch * 8);
            cp16(sbase + OFF_B + (uint32_t)r * ASTB + ch * 16,
                 g_cb + (size_t)r * KPAD + ch * 8);
        }
        CP_COMMIT();
    }

    for (int chunk = 0; chunk < NCHUNK; chunk++) {
        const int n0 = chunk * TN;

        // chunk metadata into smem (visible after first kb sync)
        if (tid < TN) {
            c2S[tid]  = g_c2[n0 + tid];
            is2S[tid] = g_is2[n0 + tid];
        }
        // Wcol[c][o] = W[o][n0+c]
        for (int idx = tid; idx < TN * OUT_DIM; idx += NTHREADS) {
            int c = idx / OUT_DIM, o = idx - c * OUT_DIM;
            WcolS[c * WST + o] = W[(size_t)o * C_DIM + n0 + c];
        }

        float acc[2][8][4];
        #pragma unroll
        for (int i = 0; i < 2; i++)
            #pragma unroll
            for (int j = 0; j < 8; j++)
                #pragma unroll
                for (int e = 0; e < 4; e++) acc[i][j][e] = 0.f;

        for (int kb = 0; kb < NKB; kb++) {
            const int g   = chunk * NKB + kb;
            const int buf = g & 1;
            CP_WAIT0();
            __syncthreads();   // tile(g) + this chunk's metadata visible

            // prefetch g+1 (crosses chunk boundary -> overlaps epilogue too)
            if (g + 1 < NGBLK) {
                const int gn    = g + 1;
                const int nchk  = gn / NKB;
                const int nkb   = gn - nchk * NKB;
                const int nn0   = nchk * TN;
                const int koff  = nkb * KB;
                const uint32_t obuf = (uint32_t)(gn & 1) * 18432u;
                #pragma unroll
                for (int i = 0; i < 4; i++) {
                    int idx = tid + i * NTHREADS;
                    int r = idx >> 3, ch = idx & 7;
                    cp16(sbase + OFF_A + obuf + (uint32_t)r * ASTB + ch * 16,
                         g_xb + (size_t)(m0 + r) * KPAD + koff + ch * 8);
                    cp16(sbase + OFF_B + obuf + (uint32_t)r * ASTB + ch * 16,
                         g_cb + (size_t)(nn0 + r) * KPAD + koff + ch * 8);
                }
                CP_COMMIT();
            }

            const uint32_t aBase = sbase + OFF_A + (uint32_t)buf * 18432u;
            const uint32_t bBase = sbase + OFF_B + (uint32_t)buf * 18432u;
            const uint32_t lrow  = (uint32_t)(lane & 15);
            const uint32_t lcol  = (uint32_t)(lane >> 4) * 16u;

            #pragma unroll
            for (int ks = 0; ks < 4; ks++) {
                uint32_t af[2][4];
                #pragma unroll
                for (int mi = 0; mi < 2; mi++)
                    ldm_x4(af[mi], aBase + (uint32_t)(wm * 32 + mi * 16 + lrow) * ASTB
                                         + (uint32_t)ks * 32u + lcol);
                uint32_t bf[8][2];
                #pragma unroll
                for (int njj = 0; njj < 4; njj++) {
                    uint32_t r4[4];
                    ldm_x4(r4, bBase + (uint32_t)(wn * 64 + njj * 16 + lrow) * ASTB
                                     + (uint32_t)ks * 32u + lcol);
                    bf[njj * 2 + 0][0] = r4[0];
                    bf[njj * 2 + 1][0] = r4[1];
                    bf[njj * 2 + 0][1] = r4[2];
                    bf[njj * 2 + 1][1] = r4[3];
                }
                #pragma unroll
                for (int mi = 0; mi < 2; mi++)
                    #pragma unroll
                    for (int nf = 0; nf < 8; nf++)
                        mma16816(acc[mi][nf], af[mi], bf[nf]);
            }
        }

        // ---- register epilogue: phi -> oacc, no smem round-trip ----
        const float x2a0 = x2S[wm * 32 + lm];          // mi=0 rows
        const float x2b0 = x2S[wm * 32 + 8 + lm];
        const float x2a1 = x2S[wm * 32 + 16 + lm];     // mi=1 rows
        const float x2b1 = x2S[wm * 32 + 24 + lm];

        #pragma unroll
        for (int nf = 0; nf < 8; nf++) {
            const int c0 = wn * 64 + nf * 8 + ln;
            const int c1 = c0 + 1;
            const float cc0 = c2S[c0],  cc1 = c2S[c1];
            const float ii0 = is2S[c0], ii1 = is2S[c1];
            float w0[OUT_DIM], w1[OUT_DIM];
            #pragma unroll
            for (int o = 0; o < OUT_DIM; o++) {
                w0[o] = WcolS[c0 * WST + o];
                w1[o] = WcolS[c1 * WST + o];
            }
            #pragma unroll
            for (int mi = 0; mi < 2; mi++) {
                const float xa = mi ? x2a1 : x2a0;
                const float xb = mi ? x2b1 : x2b0;
                const float p00 = __expf(-fmaxf(xa + cc0 - 2.f * acc[mi][nf][0], 0.f) * ii0);
                const float p01 = __expf(-fmaxf(xa + cc1 - 2.f * acc[mi][nf][1], 0.f) * ii1);
                const float p10 = __expf(-fmaxf(xb + cc0 - 2.f * acc[mi][nf][2], 0.f) * ii0);
                const float p11 = __expf(-fmaxf(xb + cc1 - 2.f * acc[mi][nf][3], 0.f) * ii1);
                #pragma unroll
                for (int o = 0; o < OUT_DIM; o++) {
                    oacc[mi * 2 + 0][o] = fmaf(p00, w0[o], fmaf(p01, w1[o], oacc[mi * 2 + 0][o]));
                    oacc[mi * 2 + 1][o] = fmaf(p10, w0[o], fmaf(p11, w1[o], oacc[mi * 2 + 1][o]));
                }
            }
        }
        __syncthreads();   // Wcol/c2/is2 consumed; next chunk may overwrite
    }

    // ---- final reduction ----
    // 1) sum the 4 lanes sharing each row (lane groups of 4, ln varies)
    #pragma unroll
    for (int i = 0; i < 4; i++)
        #pragma unroll
        for (int o = 0; o < OUT_DIM; o++) {
            float v = oacc[i][o];
            v += __shfl_xor_sync(0xffffffffu, v, 1);
            v += __shfl_xor_sync(0xffffffffu, v, 2);
            oacc[i][o] = v;
        }

    // 2) combine the two N-halves (wn=0 / wn=1) via smem (overlays A buffer)
    float* redS = (float*)(sm + OFF_RED);
    if (wn == 0 && (lane & 3) == 0) {
        #pragma unroll
        for (int i = 0; i < 4; i++) {
            const int r = wm * 32 + (i >> 1) * 16 + (i & 1) * 8 + lm;
            #pragma unroll
            for (int o = 0; o < OUT_DIM; o++) redS[r * WST + o] = oacc[i][o];
        }
    }
    __syncthreads();
    if (wn == 1 && (lane & 3) == 0) {
        #pragma unroll
        for (int i = 0; i < 4; i++) {
            const int r = wm * 32 + (i >> 1) * 16 + (i & 1) * 8 + lm;
            #pragma unroll
            for (int o = 0; o < OUT_DIM; o++) redS[r * WST + o] += oacc[i][o];
        }
    }
    __syncthreads();

    // 3) write out with bias
    for (int e = tid; e < TM * OUT_DIM; e += NTHREADS) {
        const int r = e / OUT_DIM;
        const int o = e - r * OUT_DIM;
        out[(size_t)(m0 + r) * OUT_DIM + o] = redS[r * WST + o] + __ldg(&bias[o]);
    }
}

// ---------------------------------------------------------------------------
// Launch
// ---------------------------------------------------------------------------
extern "C" void kernel_launch(void* const* d_in, const int* in_sizes, int n_in,
                              void* d_out, int out_size) {
    const float* x       = (const float*)d_in[0];
    const float* centres = (const float*)d_in[1];
    const float* ls      = (const float*)d_in[2];
    const float* W       = (const float*)d_in[3];
    const float* bias    = (const float*)d_in[4];
    float* out           = (float*)d_out;

    prep_x_kernel<<<B_ROWS / 8, 256>>>(x);
    prep_c_kernel<<<C_DIM / 8, 256>>>(centres, ls);

    cudaFuncSetAttribute(rbf_mma_kernel,
                         cudaFuncAttributeMaxDynamicSharedMemorySize, SMEM_TOTAL);
    rbf_mma_kernel<<<B_ROWS / TM, NTHREADS, SMEM_TOTAL>>>(W, bias, out);
}

// round 5
// speedup vs baseline: 14.7218x; 1.1266x over previous
#include <cuda_runtime.h>
#include <cuda_bf16.h>
#include <cuda_fp8.h>
#include <cstdint>

// ---------------------------------------------------------------------------
// Problem constants
// ---------------------------------------------------------------------------
#define B_ROWS  16384
#define D_DIM   784
#define C_DIM   2048
#define OUT_DIM 10

#define KPAD  832                // 784 padded to 13*64 (fp8 bytes)
#define KW    208                // KPAD/4 words per row
#define KB    64                 // K elems (bytes) per pipeline block
#define NKB   13
#define TM    128                // x rows per CTA
#define TN    128                // centres per chunk
#define NCHUNK (C_DIM / TN)      // 16
#define NGBLK  (NCHUNK * NKB)    // 208 flattened k-blocks
#define NTHREADS 256

// smem strides (fp8 tile row: 64 data + 16 pad bytes)
#define ASTB  80
#define TILEB 10240u             // 128 * 80
#define WST   12                 // floats per Wcol row (10 + 2 pad)

// smem byte offsets
#define OFF_A    0u              // 2 x 10240 = 20480
#define OFF_B    20480u          // 2 x 10240 = 20480
#define OFF_WCOL 40960u          // 128 x 12 x 4 = 6144
#define OFF_X2   47104u          // 128 x 4
#define OFF_C2   47616u
#define OFF_IS2  48128u
#define SMEM_TOTAL 48640u
#define OFF_RED  OFF_A           // final reduction overlays A buffer

// ---------------------------------------------------------------------------
// Device-global scratch (no allocations allowed)
// ---------------------------------------------------------------------------
__device__ __align__(16) uint32_t g_xq[(size_t)B_ROWS * KW];   // 13.6 MB fp8
__device__ __align__(16) uint32_t g_cq[(size_t)C_DIM * KW];    // 1.7 MB fp8
__device__ float g_x2[B_ROWS];
__device__ float g_c2[C_DIM];
__device__ float g_is2[C_DIM];

// ---------------------------------------------------------------------------
// PTX helpers (base-ISA sm_80/sm_89 era; valid for compute_103 virtual arch)
// ---------------------------------------------------------------------------
__device__ __forceinline__ uint32_t smem_u32(const void* p) {
    uint32_t a;
    asm("{ .reg .u64 t; cvta.to.shared.u64 t, %1; cvt.u32.u64 %0, t; }" : "=r"(a) : "l"(p));
    return a;
}

__device__ __forceinline__ void cp16(uint32_t dst, const void* src) {
    asm volatile("cp.async.cg.shared.global [%0], [%1], 16;" :: "r"(dst), "l"(src));
}
#define CP_COMMIT() asm volatile("cp.async.commit_group;" ::: "memory")
#define CP_WAIT0()  asm volatile("cp.async.wait_group 0;"  ::: "memory")

__device__ __forceinline__ void ldm_x4(uint32_t* r, uint32_t addr) {
    asm volatile("ldmatrix.sync.aligned.m8n8.x4.shared.b16 {%0,%1,%2,%3}, [%4];"
                 : "=r"(r[0]), "=r"(r[1]), "=r"(r[2]), "=r"(r[3]) : "r"(addr));
}

// fp8 e4m3 MMA: m16n8k32, f32 accum (sm_89+ base ISA)
__device__ __forceinline__ void mma16832_fp8(float* c, const uint32_t* a, const uint32_t* b) {
    asm volatile(
        "mma.sync.aligned.m16n8k32.row.col.f32.e4m3.e4m3.f32 "
        "{%0,%1,%2,%3}, {%4,%5,%6,%7}, {%8,%9}, {%0,%1,%2,%3};"
        : "+f"(c[0]), "+f"(c[1]), "+f"(c[2]), "+f"(c[3])
        : "r"(a[0]), "r"(a[1]), "r"(a[2]), "r"(a[3]), "r"(b[0]), "r"(b[1]));
}

__device__ __forceinline__ uint32_t quad_to_fp8(float4 v) {
    __nv_fp8x2_storage_t lo = __nv_cvt_float2_to_fp8x2(make_float2(v.x, v.y),
                                                       __NV_SATFINITE, __NV_E4M3);
    __nv_fp8x2_storage_t hi = __nv_cvt_float2_to_fp8x2(make_float2(v.z, v.w),
                                                       __NV_SATFINITE, __NV_E4M3);
    return (uint32_t)lo | ((uint32_t)hi << 16);
}

// ---------------------------------------------------------------------------
// Prep: quantize to padded fp8 + row squared norms (fused). One warp per row.
// 784 = 4*196, so word slots 0..195 are full float4 loads; 196..207 are pad.
// ---------------------------------------------------------------------------
__global__ void prep_x_kernel(const float* __restrict__ x) {
    int row  = (blockIdx.x * blockDim.x + threadIdx.x) >> 5;
    int lane = threadIdx.x & 31;
    if (row >= B_ROWS) return;
    const float4* src = (const float4*)(x + (size_t)row * D_DIM);
    uint32_t* dst = g_xq + (size_t)row * KW;
    float s = 0.f;
    for (int w = lane; w < KW; w += 32) {
        float4 v = (w < D_DIM / 4) ? src[w] : make_float4(0.f, 0.f, 0.f, 0.f);
        s = fmaf(v.x, v.x, fmaf(v.y, v.y, fmaf(v.z, v.z, fmaf(v.w, v.w, s))));
        dst[w] = quad_to_fp8(v);
    }
    #pragma unroll
    for (int m = 16; m; m >>= 1) s += __shfl_xor_sync(0xffffffffu, s, m);
    if (lane == 0) g_x2[row] = s;
}

__global__ void prep_c_kernel(const float* __restrict__ c, const float* __restrict__ ls) {
    int row  = (blockIdx.x * blockDim.x + threadIdx.x) >> 5;
    int lane = threadIdx.x & 31;
    if (row >= C_DIM) return;
    const float4* src = (const float4*)(c + (size_t)row * D_DIM);
    uint32_t* dst = g_cq + (size_t)row * KW;
    float s = 0.f;
    for (int w = lane; w < KW; w += 32) {
        float4 v = (w < D_DIM / 4) ? src[w] : make_float4(0.f, 0.f, 0.f, 0.f);
        s = fmaf(v.x, v.x, fmaf(v.y, v.y, fmaf(v.z, v.z, fmaf(v.w, v.w, s))));
        dst[w] = quad_to_fp8(v);
    }
    #pragma unroll
    for (int m = 16; m; m >>= 1) s += __shfl_xor_sync(0xffffffffu, s, m);
    if (lane == 0) { g_c2[row] = s; g_is2[row] = __expf(-2.f * ls[row]); }
}

// ---------------------------------------------------------------------------
// Main fused kernel: fp8 mma, register epilogue with exact underflow skip
// ---------------------------------------------------------------------------
__global__ __launch_bounds__(NTHREADS, 1)
void rbf_mma_kernel(const float* __restrict__ W,
                    const float* __restrict__ bias,
                    float* __restrict__ out) {
    extern __shared__ char sm[];
    const uint32_t sbase = smem_u32(sm);

    const int tid  = threadIdx.x;
    const int wid  = tid >> 5;
    const int lane = tid & 31;
    const int wm   = wid & 3;        // warp M group: rows wm*32 .. +31
    const int wn   = wid >> 2;       // warp N group: cols wn*64 .. +63
    const int m0   = blockIdx.x * TM;
    const int lm   = lane >> 2;      // 0..7
    const int ln   = (lane & 3) * 2; // 0,2,4,6

    float* x2S   = (float*)(sm + OFF_X2);
    float* c2S   = (float*)(sm + OFF_C2);
    float* is2S  = (float*)(sm + OFF_IS2);
    float* WcolS = (float*)(sm + OFF_WCOL);

    if (tid < TM) x2S[tid] = g_x2[m0 + tid];

    float oacc[4][OUT_DIM];
    #pragma unroll
    for (int i = 0; i < 4; i++)
        #pragma unroll
        for (int o = 0; o < OUT_DIM; o++) oacc[i][o] = 0.f;

    // cp.async tile mapping: 512 16B-chunks per tile / 256 thr = 2 each
    // idx -> row = idx>>2, ch = idx&3  (row is 64 data bytes = 4 chunks)

    // preload g = 0 -> buf 0
    {
        #pragma unroll
        for (int i = 0; i < 2; i++) {
            int idx = tid + i * NTHREADS;
            int r = idx >> 2, ch = idx & 3;
            cp16(sbase + OFF_A + (uint32_t)r * ASTB + ch * 16,
                 (const char*)(g_xq + (size_t)(m0 + r) * KW) + ch * 16);
            cp16(sbase + OFF_B + (uint32_t)r * ASTB + ch * 16,
                 (const char*)(g_cq + (size_t)r * KW) + ch * 16);
        }
        CP_COMMIT();
    }

    for (int chunk = 0; chunk < NCHUNK; chunk++) {
        const int n0 = chunk * TN;

        if (tid < TN) {
            c2S[tid]  = g_c2[n0 + tid];
            is2S[tid] = g_is2[n0 + tid];
        }
        for (int idx = tid; idx < TN * OUT_DIM; idx += NTHREADS) {
            int c = idx / OUT_DIM, o = idx - c * OUT_DIM;
            WcolS[c * WST + o] = W[(size_t)o * C_DIM + n0 + c];
        }

        float acc[2][8][4];
        #pragma unroll
        for (int i = 0; i < 2; i++)
            #pragma unroll
            for (int j = 0; j < 8; j++)
                #pragma unroll
                for (int e = 0; e < 4; e++) acc[i][j][e] = 0.f;

        for (int kb = 0; kb < NKB; kb++) {
            const int g   = chunk * NKB + kb;
            const int buf = g & 1;
            CP_WAIT0();
            __syncthreads();   // tile(g) + chunk metadata visible

            if (g + 1 < NGBLK) {
                const int gn   = g + 1;
                const int nchk = gn / NKB;
                const int nkb  = gn - nchk * NKB;
                const int nn0  = nchk * TN;
                const int koff = nkb * KB;       // byte offset into row
                const uint32_t obuf = (uint32_t)(gn & 1) * TILEB;
                #pragma unroll
                for (int i = 0; i < 2; i++) {
                    int idx = tid + i * NTHREADS;
                    int r = idx >> 2, ch = idx & 3;
                    cp16(sbase + OFF_A + obuf + (uint32_t)r * ASTB + ch * 16,
                         (const char*)(g_xq + (size_t)(m0 + r) * KW) + koff + ch * 16);
                    cp16(sbase + OFF_B + obuf + (uint32_t)r * ASTB + ch * 16,
                         (const char*)(g_cq + (size_t)(nn0 + r) * KW) + koff + ch * 16);
                }
                CP_COMMIT();
            }

            const uint32_t aBase = sbase + OFF_A + (uint32_t)buf * TILEB;
            const uint32_t bBase = sbase + OFF_B + (uint32_t)buf * TILEB;
            const uint32_t lrow  = (uint32_t)(lane & 15);
            const uint32_t lcol  = (uint32_t)(lane >> 4) * 16u;

            #pragma unroll
            for (int ks = 0; ks < 2; ks++) {         // 2 x k32 per 64-byte block
                uint32_t af[2][4];
                #pragma unroll
                for (int mi = 0; mi < 2; mi++)
                    ldm_x4(af[mi], aBase + (uint32_t)(wm * 32 + mi * 16 + lrow) * ASTB
                                         + (uint32_t)ks * 32u + lcol);
                uint32_t bf[8][2];
                #pragma unroll
                for (int njj = 0; njj < 4; njj++) {
                    uint32_t r4[4];
                    ldm_x4(r4, bBase + (uint32_t)(wn * 64 + njj * 16 + lrow) * ASTB
                                     + (uint32_t)ks * 32u + lcol);
                    bf[njj * 2 + 0][0] = r4[0];
                    bf[njj * 2 + 1][0] = r4[1];
                    bf[njj * 2 + 0][1] = r4[2];
                    bf[njj * 2 + 1][1] = r4[3];
                }
                #pragma unroll
                for (int mi = 0; mi < 2; mi++)
                    #pragma unroll
                    for (int nf = 0; nf < 8; nf++)
                        mma16832_fp8(acc[mi][nf], af[mi], bf[nf]);
            }
        }

        // ---- register epilogue with exact underflow skip ----
        // t = d2 * inv_sigma2; exp(-t) == 0.0f exactly (incl. denormals) for
        // t > 104, so skipping the exp+FMA block is bit-exact, input-generic.
        const float x2a0 = x2S[wm * 32 + lm];
        const float x2b0 = x2S[wm * 32 + 8 + lm];
        const float x2a1 = x2S[wm * 32 + 16 + lm];
        const float x2b1 = x2S[wm * 32 + 24 + lm];

        #pragma unroll
        for (int nf = 0; nf < 8; nf++) {
            const int c0 = wn * 64 + nf * 8 + ln;
            const int c1 = c0 + 1;
            const float cc0 = c2S[c0],  cc1 = c2S[c1];
            const float ii0 = is2S[c0], ii1 = is2S[c1];
            #pragma unroll
            for (int mi = 0; mi < 2; mi++) {
                const float xa = mi ? x2a1 : x2a0;
                const float xb = mi ? x2b1 : x2b0;
                const float t00 = fmaxf(xa + cc0 - 2.f * acc[mi][nf][0], 0.f) * ii0;
                const float t01 = fmaxf(xa + cc1 - 2.f * acc[mi][nf][1], 0.f) * ii1;
                const float t10 = fmaxf(xb + cc0 - 2.f * acc[mi][nf][2], 0.f) * ii0;
                const float t11 = fmaxf(xb + cc1 - 2.f * acc[mi][nf][3], 0.f) * ii1;
                if (t00 < 104.f || t01 < 104.f || t10 < 104.f || t11 < 104.f) {
                    const float p00 = __expf(-t00);
                    const float p01 = __expf(-t01);
                    const float p10 = __expf(-t10);
                    const float p11 = __expf(-t11);
                    #pragma unroll
                    for (int o = 0; o < OUT_DIM; o++) {
                        const float w0 = WcolS[c0 * WST + o];
                        const float w1 = WcolS[c1 * WST + o];
                        oacc[mi * 2 + 0][o] = fmaf(p00, w0, fmaf(p01, w1, oacc[mi * 2 + 0][o]));
                        oacc[mi * 2 + 1][o] = fmaf(p10, w0, fmaf(p11, w1, oacc[mi * 2 + 1][o]));
                    }
                }
            }
        }
        __syncthreads();   // Wcol/c2/is2 consumed; next chunk may overwrite
    }

    // ---- final reduction ----
    #pragma unroll
    for (int i = 0; i < 4; i++)
        #pragma unroll
        for (int o = 0; o < OUT_DIM; o++) {
            float v = oacc[i][o];
            v += __shfl_xor_sync(0xffffffffu, v, 1);
            v += __shfl_xor_sync(0xffffffffu, v, 2);
            oacc[i][o] = v;
        }

    float* redS = (float*)(sm + OFF_RED);
    if (wn == 0 && (lane & 3) == 0) {
        #pragma unroll
        for (int i = 0; i < 4; i++) {
            const int r = wm * 32 + (i >> 1) * 16 + (i & 1) * 8 + lm;
            #pragma unroll
            for (int o = 0; o < OUT_DIM; o++) redS[r * WST + o] = oacc[i][o];
        }
    }
    __syncthreads();
    if (wn == 1 && (lane & 3) == 0) {
        #pragma unroll
        for (int i = 0; i < 4; i++) {
            const int r = wm * 32 + (i >> 1) * 16 + (i & 1) * 8 + lm;
            #pragma unroll
            for (int o = 0; o < OUT_DIM; o++) redS[r * WST + o] += oacc[i][o];
        }
    }
    __syncthreads();

    for (int e = tid; e < TM * OUT_DIM; e += NTHREADS) {
        const int r = e / OUT_DIM;
        const int o = e - r * OUT_DIM;
        out[(size_t)(m0 + r) * OUT_DIM + o] = redS[r * WST + o] + __ldg(&bias[o]);
    }
}

// ---------------------------------------------------------------------------
// Launch
// ---------------------------------------------------------------------------
extern "C" void kernel_launch(void* const* d_in, const int* in_sizes, int n_in,
                              void* d_out, int out_size) {
    const float* x       = (const float*)d_in[0];
    const float* centres = (const float*)d_in[1];
    const float* ls      = (const float*)d_in[2];
    const float* W       = (const float*)d_in[3];
    const float* bias    = (const float*)d_in[4];
    float* out           = (float*)d_out;

    prep_x_kernel<<<B_ROWS / 8, 256>>>(x);
    prep_c_kernel<<<C_DIM / 8, 256>>>(centres, ls);

    cudaFuncSetAttribute(rbf_mma_kernel,
                         cudaFuncAttributeMaxDynamicSharedMemorySize, SMEM_TOTAL);
    rbf_mma_kernel<<<B_ROWS / TM, NTHREADS, SMEM_TOTAL>>>(W, bias, out);
}